// round 1
// baseline (speedup 1.0000x reference)
#include <cuda_runtime.h>

// RNN_40733469835755: 10-layer Elman RNN (tanh) + MLP head, fused single kernel.
// B=2048, T=512, D=8, H=20, L=10.
// 128 blocks x 160 threads; block owns 16 batch rows for the whole sequence.
// Thread (jp, bb) computes hidden units j=jp and j=jp+10 for batch row bb.
// Math uses Blackwell packed fp32 FMA (fma.rn.f32x2) with k-pair packing so
// both operands load directly from shared memory (no packing MOVs).

#define Tn 512
#define Dn 8
#define Hn 20
#define Ln 10
#define BQ 16          // batch rows per block
#define NT 160         // 10 j-pairs * 16 batch rows
#define NB 128         // 2048 / 16

typedef unsigned long long u64;

struct __align__(16) Smem {
  float wih0[Hn * Dn];              // 160
  float wih[(Ln - 1) * Hn * Hn];    // 3600
  float whh[Ln * Hn * Hn];          // 4000
  float bsum[Ln * Hn];              // 200 (b_ih + b_hh folded)
  float fcw[Hn * Hn];               // 400
  float fcb[Hn];                    // 20
  float l2w[Hn];                    // 20
  float l2b[4];                     // 1 + pad to 16B
  float hbuf[2][Ln][BQ][Hn];        // 6400: double-buffered hidden state
  float xbuf[2][BQ][Dn];            // 256:  double-buffered x_t tile
  float part[Hn / 2][BQ];           // 160:  head partial sums
};

__device__ __forceinline__ u64 fma2(u64 a, u64 b, u64 c) {
  u64 d;
  asm("fma.rn.f32x2 %0, %1, %2, %3;" : "=l"(d) : "l"(a), "l"(b), "l"(c));
  return d;
}
__device__ __forceinline__ float f2lo(u64 v) { return __uint_as_float((unsigned)v); }
__device__ __forceinline__ float f2hi(u64 v) { return __uint_as_float((unsigned)(v >> 32)); }

__device__ __forceinline__ float ex2a(float x) {
  float r; asm("ex2.approx.f32 %0, %1;" : "=f"(r) : "f"(x)); return r;
}
__device__ __forceinline__ float rcpa(float x) {
  float r; asm("rcp.approx.f32 %0, %1;" : "=f"(r) : "f"(x)); return r;
}
// tanh(x) = (e^{2x}-1)/(e^{2x}+1); ex2/rcp approx err ~1e-7 rel, clamp avoids inf/inf.
__device__ __forceinline__ float tanh_fast(float x) {
  float z = fminf(fmaxf(x, -9.0f), 9.0f);
  float e = ex2a(z * 2.8853900817779268f);  // 2*log2(e)
  return (e - 1.0f) * rcpa(e + 1.0f);
}

// Dual dot product over k (length 2*N2*2 floats): outputs A (row wA) and B (row wB)
// share the activation vector 'a'. All operands are 16B-aligned shared memory.
// Accumulates into 4 independent f32x2 chains for ILP.
template <int N2>
__device__ __forceinline__ void dot2(const float* a, const float* wA, const float* wB,
                                     u64& rA0, u64& rA1, u64& rB0, u64& rB1) {
  const ulonglong2* a2  = (const ulonglong2*)a;
  const ulonglong2* wA2 = (const ulonglong2*)wA;
  const ulonglong2* wB2 = (const ulonglong2*)wB;
#pragma unroll
  for (int q = 0; q < N2; ++q) {
    ulonglong2 av = a2[q];
    ulonglong2 wa = wA2[q];
    ulonglong2 wb = wB2[q];
    rA0 = fma2(wa.x, av.x, rA0);
    rA1 = fma2(wa.y, av.y, rA1);
    rB0 = fma2(wb.x, av.x, rB0);
    rB1 = fma2(wb.y, av.y, rB1);
  }
}

__global__ __launch_bounds__(NT)
void rnn_kernel(const float* __restrict__ x,
                const float* __restrict__ g_wih0,
                const float* __restrict__ g_wih,
                const float* __restrict__ g_whh,
                const float* __restrict__ g_bih,
                const float* __restrict__ g_bhh,
                const float* __restrict__ g_fcw,
                const float* __restrict__ g_fcb,
                const float* __restrict__ g_l2w,
                const float* __restrict__ g_l2b,
                float* __restrict__ y) {
  extern __shared__ float smem_raw[];
  Smem* S = (Smem*)smem_raw;

  const int tid = threadIdx.x;
  const int jp  = tid / BQ;        // 0..9
  const int bb  = tid % BQ;        // 0..15
  const int j0  = jp;
  const int j1  = jp + Hn / 2;
  const int b0  = blockIdx.x * BQ;

  // ---- one-time init: weights -> SMEM, zero h0, load x(t=0) ----
  for (int i = tid; i < Hn * Dn; i += NT)            S->wih0[i] = g_wih0[i];
  for (int i = tid; i < (Ln - 1) * Hn * Hn; i += NT) S->wih[i]  = g_wih[i];
  for (int i = tid; i < Ln * Hn * Hn; i += NT)       S->whh[i]  = g_whh[i];
  for (int i = tid; i < Ln * Hn; i += NT)            S->bsum[i] = g_bih[i] + g_bhh[i];
  for (int i = tid; i < Hn * Hn; i += NT)            S->fcw[i]  = g_fcw[i];
  for (int i = tid; i < Hn; i += NT) { S->fcb[i] = g_fcb[i]; S->l2w[i] = g_l2w[i]; }
  if (tid == 0) S->l2b[0] = g_l2b[0];
  {
    float* h0 = &S->hbuf[0][0][0][0];
    for (int i = tid; i < Ln * BQ * Hn; i += NT) h0[i] = 0.0f;
  }
  for (int i = tid; i < BQ * Dn; i += NT) {
    int bbi = i / Dn, k = i % Dn;
    S->xbuf[0][bbi][k] = x[((size_t)(b0 + bbi) * Tn + 0) * Dn + k];
  }
  __syncthreads();

  int p = 0;
  for (int t = 0; t < Tn; ++t) {
    const int pn = p ^ 1;

    // prefetch x(t+1) into registers (warp 0: 16 rows x 2 float4)
    float4 xr = make_float4(0.f, 0.f, 0.f, 0.f);
    const bool pf = (tid < 32) && (t + 1 < Tn);
    if (pf)
      xr = *(const float4*)(x + ((size_t)(b0 + (tid >> 1)) * Tn + (t + 1)) * Dn + (tid & 1) * 4);

    // ---- layer 0 (input dim D=8) ----
    {
      u64 rA0 = 0, rA1 = 0, rB0 = 0, rB1 = 0;
      dot2<2>(&S->xbuf[p][bb][0], &S->wih0[j0 * Dn], &S->wih0[j1 * Dn], rA0, rA1, rB0, rB1);
      dot2<5>(&S->hbuf[p][0][bb][0], &S->whh[j0 * Hn], &S->whh[j1 * Hn], rA0, rA1, rB0, rB1);
      float vA = (f2lo(rA0) + f2hi(rA0)) + (f2lo(rA1) + f2hi(rA1)) + S->bsum[j0];
      float vB = (f2lo(rB0) + f2hi(rB0)) + (f2lo(rB1) + f2hi(rB1)) + S->bsum[j1];
      S->hbuf[pn][0][bb][j0] = tanh_fast(vA);
      S->hbuf[pn][0][bb][j1] = tanh_fast(vB);
    }
    __syncthreads();

    // ---- layers 1..9 ----
#pragma unroll
    for (int l = 1; l < Ln; ++l) {
      u64 rA0 = 0, rA1 = 0, rB0 = 0, rB1 = 0;
      dot2<5>(&S->hbuf[pn][l - 1][bb][0],
              &S->wih[((l - 1) * Hn + j0) * Hn], &S->wih[((l - 1) * Hn + j1) * Hn],
              rA0, rA1, rB0, rB1);
      dot2<5>(&S->hbuf[p][l][bb][0],
              &S->whh[(l * Hn + j0) * Hn], &S->whh[(l * Hn + j1) * Hn],
              rA0, rA1, rB0, rB1);
      float vA = (f2lo(rA0) + f2hi(rA0)) + (f2lo(rA1) + f2hi(rA1)) + S->bsum[l * Hn + j0];
      float vB = (f2lo(rB0) + f2hi(rB0)) + (f2lo(rB1) + f2hi(rB1)) + S->bsum[l * Hn + j1];
      S->hbuf[pn][l][bb][j0] = tanh_fast(vA);
      S->hbuf[pn][l][bb][j1] = tanh_fast(vB);
      __syncthreads();
    }

    // ---- head: y = relu(h_top @ fcw^T + fcb) @ l2w^T + l2b ----
    {
      u64 rA0 = 0, rA1 = 0, rB0 = 0, rB1 = 0;
      dot2<5>(&S->hbuf[pn][Ln - 1][bb][0], &S->fcw[j0 * Hn], &S->fcw[j1 * Hn],
              rA0, rA1, rB0, rB1);
      float vA = (f2lo(rA0) + f2hi(rA0)) + (f2lo(rA1) + f2hi(rA1)) + S->fcb[j0];
      float vB = (f2lo(rB0) + f2hi(rB0)) + (f2lo(rB1) + f2hi(rB1)) + S->fcb[j1];
      S->part[jp][bb] = fmaxf(vA, 0.0f) * S->l2w[j0] + fmaxf(vB, 0.0f) * S->l2w[j1];
      // stage prefetched x(t+1) for next step
      if (pf) *(float4*)&S->xbuf[pn][tid >> 1][(tid & 1) * 4] = xr;
    }
    __syncthreads();

    if (jp == 0) {  // lanes 0..15 of warp 0 reduce the 10 partials
      float s = S->l2b[0];
#pragma unroll
      for (int q = 0; q < Hn / 2; ++q) s += S->part[q][bb];
      y[(size_t)(b0 + bb) * Tn + t] = s;
    }

    p = pn;
  }
}

extern "C" void kernel_launch(void* const* d_in, const int* in_sizes, int n_in,
                              void* d_out, int out_size) {
  (void)in_sizes; (void)n_in; (void)out_size;
  const float* x    = (const float*)d_in[0];
  const float* wih0 = (const float*)d_in[1];
  const float* wih  = (const float*)d_in[2];
  const float* whh  = (const float*)d_in[3];
  const float* bih  = (const float*)d_in[4];
  const float* bhh  = (const float*)d_in[5];
  const float* fcw  = (const float*)d_in[6];
  const float* fcb  = (const float*)d_in[7];
  const float* l2w  = (const float*)d_in[8];
  const float* l2b  = (const float*)d_in[9];
  float* y = (float*)d_out;

  cudaFuncSetAttribute(rnn_kernel, cudaFuncAttributeMaxDynamicSharedMemorySize,
                       (int)sizeof(Smem));
  rnn_kernel<<<NB, NT, sizeof(Smem)>>>(x, wih0, wih, whh, bih, bhh,
                                       fcw, fcb, l2w, l2b, y);
}

// round 2
// speedup vs baseline: 2.2630x; 2.2630x over previous
#include <cuda_runtime.h>

// RNN_40733469835755 — wavefront-parallel 10-layer Elman RNN + MLP head.
// B=2048, T=512, D=8, H=20, L=10.
// 128 blocks x 352 threads (11 warps). Warp l (l<10) owns layer l forever;
// warp 10 runs the MLP head and prefetches x. Tick s: layer l processes
// t = s - l (diagonal wavefront) -> ONE __syncthreads per tick, 522 ticks.
// Activations live in smem as A[parity][bb][slot*20], slot0 = x (padded to 20,
// cols 8..19 stay zero), slot l+1 = layer l output. Layer l reads the
// contiguous 40-float window [slot l | slot l+1] = [input | h_prev], matching
// concatenated weight rows W[l][j][40] = [Wih(padded) | Whh]. All math uses
// Blackwell packed fma.rn.f32x2 straight out of 16B-aligned shared memory.

#define Tn 512
#define Dn 8
#define Hn 20
#define Ln 10
#define BQ 16
#define NW 11
#define NT (NW * 32)     // 352
#define NB 128           // 2048 / 16
#define SLOTS 11
#define ROWLEN (SLOTS * Hn)  // 220 floats per (parity, batch-row)

typedef unsigned long long u64;

struct __align__(16) Smem {
  float W[Ln][Hn][2 * Hn];   // 8000: concat [Wih | Whh], layer0 Wih cols 8..19 = 0
  float bsum[Ln][Hn];        // 200:  b_ih + b_hh
  float fcw[Hn][Hn];         // 400
  float fcb[Hn];             // 20
  float l2w[Hn];             // 20
  float l2b[4];              // pad to keep A 16B-aligned
  float A[2][BQ][ROWLEN];    // 7040: double-buffered activations
};

__device__ __forceinline__ u64 fma2(u64 a, u64 b, u64 c) {
  u64 d;
  asm("fma.rn.f32x2 %0, %1, %2, %3;" : "=l"(d) : "l"(a), "l"(b), "l"(c));
  return d;
}
__device__ __forceinline__ float f2lo(u64 v) { return __uint_as_float((unsigned)v); }
__device__ __forceinline__ float f2hi(u64 v) { return __uint_as_float((unsigned)(v >> 32)); }

__device__ __forceinline__ float ex2a(float x) {
  float r; asm("ex2.approx.f32 %0, %1;" : "=f"(r) : "f"(x)); return r;
}
__device__ __forceinline__ float rcpa(float x) {
  float r; asm("rcp.approx.f32 %0, %1;" : "=f"(r) : "f"(x)); return r;
}
__device__ __forceinline__ float tanh_fast(float x) {
  float z = fminf(fmaxf(x, -9.0f), 9.0f);
  float e = ex2a(z * 2.8853900817779268f);  // 2*log2(e)
  return (e - 1.0f) * rcpa(e + 1.0f);
}

__global__ __launch_bounds__(NT, 1)
void rnn_kernel(const float* __restrict__ x,
                const float* __restrict__ g_wih0,
                const float* __restrict__ g_wih,
                const float* __restrict__ g_whh,
                const float* __restrict__ g_bih,
                const float* __restrict__ g_bhh,
                const float* __restrict__ g_fcw,
                const float* __restrict__ g_fcb,
                const float* __restrict__ g_l2w,
                const float* __restrict__ g_l2b,
                float* __restrict__ y) {
  extern __shared__ float smem_raw[];
  Smem* S = (Smem*)smem_raw;

  const int tid  = threadIdx.x;
  const int wid  = tid >> 5;
  const int lane = tid & 31;
  const int b0   = blockIdx.x * BQ;

  // ---- one-time init ----
  // Concatenated weights W[l][j][k]: k<20 -> input weights (layer0 padded), k>=20 -> Whh.
  for (int i = tid; i < Ln * Hn * 2 * Hn; i += NT) {
    int k = i % (2 * Hn);
    int j = (i / (2 * Hn)) % Hn;
    int l = i / (2 * Hn * Hn);
    float v;
    if (k < Hn) {
      if (l == 0) v = (k < Dn) ? g_wih0[j * Dn + k] : 0.0f;
      else        v = g_wih[((size_t)(l - 1) * Hn + j) * Hn + k];
    } else {
      v = g_whh[((size_t)l * Hn + j) * Hn + (k - Hn)];
    }
    (&S->W[0][0][0])[i] = v;
  }
  for (int i = tid; i < Ln * Hn; i += NT) (&S->bsum[0][0])[i] = g_bih[i] + g_bhh[i];
  for (int i = tid; i < Hn * Hn; i += NT) (&S->fcw[0][0])[i] = g_fcw[i];
  if (tid < Hn) { S->fcb[tid] = g_fcb[tid]; S->l2w[tid] = g_l2w[tid]; }
  if (tid == 0) S->l2b[0] = g_l2b[0];
  for (int i = tid; i < 2 * BQ * ROWLEN; i += NT) (&S->A[0][0][0])[i] = 0.0f;
  __syncthreads();
  // x[t=0] into parity-1 slot 0 (read parity at tick 0 is 1).
  if (tid < 32) {
    int br = tid >> 1, hf = tid & 1;
    float4 v = *(const float4*)&x[((size_t)(b0 + br) * Tn + 0) * Dn + hf * 4];
    *(float4*)&S->A[1][br][hf * 4] = v;
  }
  __syncthreads();

  if (wid < Ln) {
    // ================= layer warp =================
    const int l   = wid;
    const int jq  = lane >> 3;   // 0..3  (j group: rows jq*5 .. jq*5+4)
    const int bbl = lane & 7;    // 0..7  (batch rows bbl and bbl+8)
    const float* wbase = &S->W[l][jq * 5][0];
    const float* bptr  = &S->bsum[l][jq * 5];

    for (int s = 0; s < Tn + Ln; ++s) {
      const int wp = s & 1, rp = wp ^ 1;
      const int t = s - l;
      if ((unsigned)t < (unsigned)Tn) {
        const float* a0p = &S->A[rp][bbl][l * Hn];
        const float* a1p = &S->A[rp][bbl + 8][l * Hn];
        u64 acc[5][2];
#pragma unroll
        for (int jj = 0; jj < 5; ++jj) { acc[jj][0] = 0; acc[jj][1] = 0; }
#pragma unroll
        for (int kc = 0; kc < 10; ++kc) {
          ulonglong2 a0 = *(const ulonglong2*)(a0p + kc * 4);
          ulonglong2 a1 = *(const ulonglong2*)(a1p + kc * 4);
#pragma unroll
          for (int jj = 0; jj < 5; ++jj) {
            ulonglong2 w = *(const ulonglong2*)(wbase + jj * 2 * Hn + kc * 4);
            acc[jj][0] = fma2(w.x, a0.x, fma2(w.y, a0.y, acc[jj][0]));
            acc[jj][1] = fma2(w.x, a1.x, fma2(w.y, a1.y, acc[jj][1]));
          }
        }
        float* o0 = &S->A[wp][bbl][(l + 1) * Hn + jq * 5];
        float* o1 = &S->A[wp][bbl + 8][(l + 1) * Hn + jq * 5];
#pragma unroll
        for (int jj = 0; jj < 5; ++jj) {
          float b  = bptr[jj];
          float v0 = (f2lo(acc[jj][0]) + f2hi(acc[jj][0])) + b;
          float v1 = (f2lo(acc[jj][1]) + f2hi(acc[jj][1])) + b;
          o0[jj] = tanh_fast(v0);
          o1[jj] = tanh_fast(v1);
        }
      }
      __syncthreads();
    }
  } else {
    // ================= head warp (MLP + x prefetch + y store) =================
    const int bb = lane & 15, jh = lane >> 4;
    for (int s = 0; s < Tn + Ln; ++s) {
      const int wp = s & 1, rp = wp ^ 1;
      // prefetch x[t = s+1] into parity wp, slot 0 (consumed by layer0 at tick s+1)
      const int tx = s + 1;
      if (tx < Tn) {
        int br = lane >> 1, hf = lane & 1;
        float4 v = *(const float4*)&x[((size_t)(b0 + br) * Tn + tx) * Dn + hf * 4];
        *(float4*)&S->A[wp][br][hf * 4] = v;
      }
      const int t = s - Ln;
      if ((unsigned)t < (unsigned)Tn) {
        const float* hrow = &S->A[rp][bb][Ln * Hn];  // layer-9 output (slot 10)
        u64 hv[10];
#pragma unroll
        for (int c = 0; c < 5; ++c) {
          ulonglong2 q = *(const ulonglong2*)(hrow + c * 4);
          hv[2 * c] = q.x; hv[2 * c + 1] = q.y;
        }
        float acc = 0.0f;
#pragma unroll
        for (int jj = 0; jj < 10; ++jj) {
          int j = jh * 10 + jj;
          const float* wr = &S->fcw[j][0];
          u64 d0 = 0, d1 = 0;
#pragma unroll
          for (int c = 0; c < 5; ++c) {
            ulonglong2 w = *(const ulonglong2*)(wr + c * 4);
            d0 = fma2(w.x, hv[2 * c], d0);
            d1 = fma2(w.y, hv[2 * c + 1], d1);
          }
          float v = (f2lo(d0) + f2hi(d0)) + (f2lo(d1) + f2hi(d1)) + S->fcb[j];
          acc += fmaxf(v, 0.0f) * S->l2w[j];
        }
        acc += __shfl_xor_sync(0xFFFFFFFFu, acc, 16);
        if (jh == 0) y[(size_t)(b0 + bb) * Tn + t] = acc + S->l2b[0];
      }
      __syncthreads();
    }
  }
}

extern "C" void kernel_launch(void* const* d_in, const int* in_sizes, int n_in,
                              void* d_out, int out_size) {
  (void)in_sizes; (void)n_in; (void)out_size;
  const float* x    = (const float*)d_in[0];
  const float* wih0 = (const float*)d_in[1];
  const float* wih  = (const float*)d_in[2];
  const float* whh  = (const float*)d_in[3];
  const float* bih  = (const float*)d_in[4];
  const float* bhh  = (const float*)d_in[5];
  const float* fcw  = (const float*)d_in[6];
  const float* fcb  = (const float*)d_in[7];
  const float* l2w  = (const float*)d_in[8];
  const float* l2b  = (const float*)d_in[9];
  float* y = (float*)d_out;

  cudaFuncSetAttribute(rnn_kernel, cudaFuncAttributeMaxDynamicSharedMemorySize,
                       (int)sizeof(Smem));
  rnn_kernel<<<NB, NT, sizeof(Smem)>>>(x, wih0, wih, whh, bih, bhh,
                                       fcw, fcb, l2w, l2b, y);
}

// round 3
// speedup vs baseline: 2.9455x; 1.3016x over previous
#include <cuda_runtime.h>

// RNN_40733469835755 — wavefront RNN, 2 timesteps/tick, register-resident weights.
// B=2048, T=512, D=8, H=20, L=10. 128 blocks x 352 threads (11 warps).
// Warp l owns layer l; tick s processes t = 2(s-l), 2(s-l)+1 (ONE __syncthreads
// per tick, 266 ticks). Warp 10 = MLP head + x prefetch + y store.
// Recurrent weights (cols 20..39) + biases live in registers; input weights
// stream from smem once per tick, reused across 2 timesteps x 2 batch rows.
// Activations: A[parity][u][row*220 + slot*20]; slot0 = x (cols 8..19 = 0),
// slot l+1 = layer-l output. u-plane pitch padded +16 floats for bank cover.

#define Tn 512
#define Dn 8
#define Hn 20
#define Ln 10
#define BQ 16
#define NT 352
#define NB 128
#define ROWLEN 220
#define UPITCH (BQ * ROWLEN + 16)   // 3536 floats; +16 => u-plane bank offset 16
#define NTICKS (Tn / 2 + Ln)        // 266

typedef unsigned long long u64;

struct __align__(16) Smem {
  float W[Ln][Hn][2 * Hn];   // concat [Wih(pad20) | Whh]
  float bsum[Ln][Hn];
  float fcw[Hn][Hn];
  float fcb[Hn];
  float l2w[Hn];
  float l2b[4];
  float A[2][2][UPITCH];     // [parity][u][row*ROWLEN + off]
};

__device__ __forceinline__ u64 fma2(u64 a, u64 b, u64 c) {
  u64 d;
  asm("fma.rn.f32x2 %0, %1, %2, %3;" : "=l"(d) : "l"(a), "l"(b), "l"(c));
  return d;
}
__device__ __forceinline__ float f2lo(u64 v) { return __uint_as_float((unsigned)v); }
__device__ __forceinline__ float f2hi(u64 v) { return __uint_as_float((unsigned)(v >> 32)); }

__device__ __forceinline__ float ex2a(float x) {
  float r; asm("ex2.approx.f32 %0, %1;" : "=f"(r) : "f"(x)); return r;
}
__device__ __forceinline__ float rcpa(float x) {
  float r; asm("rcp.approx.f32 %0, %1;" : "=f"(r) : "f"(x)); return r;
}
__device__ __forceinline__ float tanh_fast(float x) {
  float z = fminf(fmaxf(x, -9.0f), 9.0f);
  float e = ex2a(z * 2.8853900817779268f);  // 2*log2(e)
  return (e - 1.0f) * rcpa(e + 1.0f);
}

__global__ __launch_bounds__(NT, 1)
void rnn_kernel(const float* __restrict__ x,
                const float* __restrict__ g_wih0,
                const float* __restrict__ g_wih,
                const float* __restrict__ g_whh,
                const float* __restrict__ g_bih,
                const float* __restrict__ g_bhh,
                const float* __restrict__ g_fcw,
                const float* __restrict__ g_fcb,
                const float* __restrict__ g_l2w,
                const float* __restrict__ g_l2b,
                float* __restrict__ y) {
  extern __shared__ float smem_raw[];
  Smem* S = (Smem*)smem_raw;

  const int tid  = threadIdx.x;
  const int wid  = tid >> 5;
  const int lane = tid & 31;
  const int b0   = blockIdx.x * BQ;

  // ---- one-time init ----
  for (int i = tid; i < Ln * Hn * 2 * Hn; i += NT) {
    int k = i % (2 * Hn);
    int j = (i / (2 * Hn)) % Hn;
    int l = i / (2 * Hn * Hn);
    float v;
    if (k < Hn) {
      if (l == 0) v = (k < Dn) ? g_wih0[j * Dn + k] : 0.0f;
      else        v = g_wih[((size_t)(l - 1) * Hn + j) * Hn + k];
    } else {
      v = g_whh[((size_t)l * Hn + j) * Hn + (k - Hn)];
    }
    (&S->W[0][0][0])[i] = v;
  }
  for (int i = tid; i < Ln * Hn; i += NT) (&S->bsum[0][0])[i] = g_bih[i] + g_bhh[i];
  for (int i = tid; i < Hn * Hn; i += NT) (&S->fcw[0][0])[i] = g_fcw[i];
  if (tid < Hn) { S->fcb[tid] = g_fcb[tid]; S->l2w[tid] = g_l2w[tid]; }
  if (tid == 0) S->l2b[0] = g_l2b[0];
  for (int i = tid; i < 2 * 2 * UPITCH; i += NT) (&S->A[0][0][0])[i] = 0.0f;
  __syncthreads();
  // x[t=0], x[t=1] into read-parity (rp=1 at tick 0) planes u0/u1.
  if (tid < 32) {
    int row = tid >> 1, half = tid & 1;
    float4 v0 = *(const float4*)&x[(((size_t)(b0 + row)) * Tn + 0) * Dn + half * 4];
    float4 v1 = *(const float4*)&x[(((size_t)(b0 + row)) * Tn + 1) * Dn + half * 4];
    *(float4*)&S->A[1][0][row * ROWLEN + half * 4] = v0;
    *(float4*)&S->A[1][1][row * ROWLEN + half * 4] = v1;
  }
  __syncthreads();

  if (wid < Ln) {
    // ================= layer warp =================
    const int l   = wid;
    const int jq  = lane >> 3;   // 0..3 (rows jq*5..+4)
    const int bbl = lane & 7;    // rows bbl, bbl+8
    const float* wbase = &S->W[l][jq * 5][0];
    const int r0 = bbl * ROWLEN, r1 = (bbl + 8) * ROWLEN;

    // hoist recurrent weights (cols 20..39) + biases into registers
    ulonglong2 wr[5][5];
    float bj[5];
#pragma unroll
    for (int jj = 0; jj < 5; ++jj) {
      bj[jj] = S->bsum[l][jq * 5 + jj];
#pragma unroll
      for (int kc = 0; kc < 5; ++kc)
        wr[jj][kc] = *(const ulonglong2*)(wbase + jj * 2 * Hn + Hn + kc * 4);
    }

    for (int s = 0; s < NTICKS; ++s) {
      const int wp = s & 1, rp = wp ^ 1;
      const int t0 = 2 * (s - l);
      if (t0 >= 0 && t0 < Tn) {
        const float* Ar0 = S->A[rp][0];
        const float* Ar1 = S->A[rp][1];
        float* Aw0 = S->A[wp][0];
        float* Aw1 = S->A[wp][1];
        u64 a0[5], a1[5], c0[5], c1[5];
#pragma unroll
        for (int jj = 0; jj < 5; ++jj) { a0[jj] = 0; a1[jj] = 0; c0[jj] = 0; c1[jj] = 0; }

        // recurrent tau0: h[l][t0-1] = prev tick's tau1 output (Ar1, slot l+1)
        {
          const float* p0 = Ar1 + r0 + (l + 1) * Hn;
          const float* p1 = Ar1 + r1 + (l + 1) * Hn;
#pragma unroll
          for (int kc = 0; kc < 5; ++kc) {
            ulonglong2 v0 = *(const ulonglong2*)(p0 + kc * 4);
            ulonglong2 v1 = *(const ulonglong2*)(p1 + kc * 4);
#pragma unroll
            for (int jj = 0; jj < 5; ++jj) {
              a0[jj] = fma2(wr[jj][kc].x, v0.x, fma2(wr[jj][kc].y, v0.y, a0[jj]));
              a1[jj] = fma2(wr[jj][kc].x, v1.x, fma2(wr[jj][kc].y, v1.y, a1[jj]));
            }
          }
        }
        // input part, both timesteps: weights streamed once, reused 4x
        {
          const float* q00 = Ar0 + r0 + l * Hn;
          const float* q01 = Ar0 + r1 + l * Hn;
          const float* q10 = Ar1 + r0 + l * Hn;
          const float* q11 = Ar1 + r1 + l * Hn;
#pragma unroll
          for (int kc = 0; kc < 5; ++kc) {
            ulonglong2 x00 = *(const ulonglong2*)(q00 + kc * 4);
            ulonglong2 x01 = *(const ulonglong2*)(q01 + kc * 4);
            ulonglong2 x10 = *(const ulonglong2*)(q10 + kc * 4);
            ulonglong2 x11 = *(const ulonglong2*)(q11 + kc * 4);
#pragma unroll
            for (int jj = 0; jj < 5; ++jj) {
              ulonglong2 w = *(const ulonglong2*)(wbase + jj * 2 * Hn + kc * 4);
              a0[jj] = fma2(w.x, x00.x, fma2(w.y, x00.y, a0[jj]));
              a1[jj] = fma2(w.x, x01.x, fma2(w.y, x01.y, a1[jj]));
              c0[jj] = fma2(w.x, x10.x, fma2(w.y, x10.y, c0[jj]));
              c1[jj] = fma2(w.x, x11.x, fma2(w.y, x11.y, c1[jj]));
            }
          }
        }
        // finish tau0, publish for intra-tick recurrence
        {
          float* o0 = Aw0 + r0 + (l + 1) * Hn + jq * 5;
          float* o1 = Aw0 + r1 + (l + 1) * Hn + jq * 5;
#pragma unroll
          for (int jj = 0; jj < 5; ++jj) {
            o0[jj] = tanh_fast(f2lo(a0[jj]) + f2hi(a0[jj]) + bj[jj]);
            o1[jj] = tanh_fast(f2lo(a1[jj]) + f2hi(a1[jj]) + bj[jj]);
          }
        }
        __syncwarp();
        // recurrent tau1: reads tau0 output (Aw0, slot l+1), reuses reg weights
        {
          const float* s0p = Aw0 + r0 + (l + 1) * Hn;
          const float* s1p = Aw0 + r1 + (l + 1) * Hn;
#pragma unroll
          for (int kc = 0; kc < 5; ++kc) {
            ulonglong2 v0 = *(const ulonglong2*)(s0p + kc * 4);
            ulonglong2 v1 = *(const ulonglong2*)(s1p + kc * 4);
#pragma unroll
            for (int jj = 0; jj < 5; ++jj) {
              c0[jj] = fma2(wr[jj][kc].x, v0.x, fma2(wr[jj][kc].y, v0.y, c0[jj]));
              c1[jj] = fma2(wr[jj][kc].x, v1.x, fma2(wr[jj][kc].y, v1.y, c1[jj]));
            }
          }
          float* e0 = Aw1 + r0 + (l + 1) * Hn + jq * 5;
          float* e1 = Aw1 + r1 + (l + 1) * Hn + jq * 5;
#pragma unroll
          for (int jj = 0; jj < 5; ++jj) {
            e0[jj] = tanh_fast(f2lo(c0[jj]) + f2hi(c0[jj]) + bj[jj]);
            e1[jj] = tanh_fast(f2lo(c1[jj]) + f2hi(c1[jj]) + bj[jj]);
          }
        }
      }
      __syncthreads();
    }
  } else {
    // ================= head warp =================
    const int u  = lane >> 4;        // timestep within tick
    const int jq = (lane >> 2) & 3;  // fc rows jq*5..+4
    const int bq = lane & 3;         // rows bq, bq+4, bq+8, bq+12

    ulonglong2 wf[5][5];
    float fb[5], lw[5];
#pragma unroll
    for (int jj = 0; jj < 5; ++jj) {
      fb[jj] = S->fcb[jq * 5 + jj];
      lw[jj] = S->l2w[jq * 5 + jj];
#pragma unroll
      for (int kc = 0; kc < 5; ++kc)
        wf[jj][kc] = *(const ulonglong2*)(&S->fcw[jq * 5 + jj][0] + kc * 4);
    }
    const float l2b0 = S->l2b[0];
    const int xrow = lane >> 1, xhalf = lane & 1;

    for (int s = 0; s < NTICKS; ++s) {
      const int wp = s & 1, rp = wp ^ 1;
      // prefetch x for tick s+1 (t = 2(s+1), 2(s+1)+1)
      const int tx = 2 * (s + 1);
      if (tx < Tn) {
        float4 v0 = *(const float4*)&x[(((size_t)(b0 + xrow)) * Tn + tx) * Dn + xhalf * 4];
        float4 v1 = *(const float4*)&x[(((size_t)(b0 + xrow)) * Tn + tx + 1) * Dn + xhalf * 4];
        *(float4*)&S->A[wp][0][xrow * ROWLEN + xhalf * 4] = v0;
        *(float4*)&S->A[wp][1][xrow * ROWLEN + xhalf * 4] = v1;
      }
      const int t0h = 2 * (s - Ln);
      if (t0h >= 0) {
        const float* Au = S->A[rp][u];
        float psum[4];
#pragma unroll
        for (int i = 0; i < 4; ++i) {
          const float* hrow = Au + (bq + 4 * i) * ROWLEN + Ln * Hn;  // slot 10
          ulonglong2 hv[5];
#pragma unroll
          for (int kc = 0; kc < 5; ++kc) hv[kc] = *(const ulonglong2*)(hrow + kc * 4);
          float p = 0.0f;
#pragma unroll
          for (int jj = 0; jj < 5; ++jj) {
            u64 d0 = 0, d1 = 0;
#pragma unroll
            for (int kc = 0; kc < 5; ++kc) {
              d0 = fma2(wf[jj][kc].x, hv[kc].x, d0);
              d1 = fma2(wf[jj][kc].y, hv[kc].y, d1);
            }
            float v = f2lo(d0) + f2hi(d0) + f2lo(d1) + f2hi(d1) + fb[jj];
            p += fmaxf(v, 0.0f) * lw[jj];
          }
          psum[i] = p;
        }
#pragma unroll
        for (int i = 0; i < 4; ++i) {
          psum[i] += __shfl_xor_sync(0xFFFFFFFFu, psum[i], 4);
          psum[i] += __shfl_xor_sync(0xFFFFFFFFu, psum[i], 8);
        }
        if (jq == 0) {
#pragma unroll
          for (int i = 0; i < 4; ++i)
            y[(size_t)(b0 + bq + 4 * i) * Tn + t0h + u] = psum[i] + l2b0;
        }
      }
      __syncthreads();
    }
  }
}

extern "C" void kernel_launch(void* const* d_in, const int* in_sizes, int n_in,
                              void* d_out, int out_size) {
  (void)in_sizes; (void)n_in; (void)out_size;
  const float* x    = (const float*)d_in[0];
  const float* wih0 = (const float*)d_in[1];
  const float* wih  = (const float*)d_in[2];
  const float* whh  = (const float*)d_in[3];
  const float* bih  = (const float*)d_in[4];
  const float* bhh  = (const float*)d_in[5];
  const float* fcw  = (const float*)d_in[6];
  const float* fcb  = (const float*)d_in[7];
  const float* l2w  = (const float*)d_in[8];
  const float* l2b  = (const float*)d_in[9];
  float* y = (float*)d_out;

  cudaFuncSetAttribute(rnn_kernel, cudaFuncAttributeMaxDynamicSharedMemorySize,
                       (int)sizeof(Smem));
  rnn_kernel<<<NB, NT, sizeof(Smem)>>>(x, wih0, wih, whh, bih, bhh,
                                       fcw, fcb, l2w, l2b, y);
}